// round 3
// baseline (speedup 1.0000x reference)
#include <cuda_runtime.h>

#define CUT0   2000
#define CUT1   20000
#define BATCH  8192
#define HDIM   1024
#define H4     256
#define NCOLS0 18000
#define NCOLS1 30000
#define HEADC  2002

// ---------------- device scratch (no allocations allowed) ----------------
__device__ int   d_idx0[BATCH];
__device__ int   d_idx1[BATCH];
__device__ int   d_counts[2];
__device__ float d_dec0[18432000];  // 18000 x 1024
__device__ float d_dec1[7680000];   // 30000 x 256
__device__ float d_h0[8388608];     // 8192 x 1024
__device__ float d_h1[2097152];     // 8192 x 256

// packed f32x2 helpers (Blackwell)
#define PACK2(d, x, y) asm("mov.b64 %0, {%1, %2};" : "=l"(d) : "f"(x), "f"(y))
#define UNPACK2(x, y, d) asm("mov.b64 {%0, %1}, %2;" : "=f"(x), "=f"(y) : "l"(d))
#define FMA2(acc, a, b) asm("fma.rn.f32x2 %0, %1, %2, %0;" : "+l"(acc) : "l"(a), "l"(b))

// ---------------- partition targets into cluster index lists -------------
// One block, 1024 threads, 8 targets each. Stable (ascending) order matches
// np.nonzero. Handles BOTH int32 and int64 target buffers (JAX without x64
// silently downcasts int64 -> int32): detect layout on-device.
__global__ void scan_targets_kernel(const int* __restrict__ tw) {
    __shared__ int s0[1024], s1[1024];
    __shared__ int anynz;
    int t = threadIdx.x;
    if (t == 0) anynz = 0;
    __syncthreads();
    int nz = 0;
#pragma unroll
    for (int i = t; i < 4096; i += 1024)
        nz |= (tw[2 * i + 1] != 0);
    if (nz) atomicOr(&anynz, 1);
    __syncthreads();
    int stride = anynz ? 1 : 2;   // int32 : int64

    int v[8];
    int c0 = 0, c1 = 0;
#pragma unroll
    for (int i = 0; i < 8; i++) {
        v[i] = tw[(t * 8 + i) * stride];
        c0 += (v[i] >= CUT0 && v[i] < CUT1) ? 1 : 0;
        c1 += (v[i] >= CUT1) ? 1 : 0;
    }
    s0[t] = c0; s1[t] = c1;
    __syncthreads();
    for (int off = 1; off < 1024; off <<= 1) {
        int a0 = (t >= off) ? s0[t - off] : 0;
        int a1 = (t >= off) ? s1[t - off] : 0;
        __syncthreads();
        s0[t] += a0; s1[t] += a1;
        __syncthreads();
    }
    int p0 = s0[t] - c0, p1 = s1[t] - c1;   // exclusive prefix
#pragma unroll
    for (int i = 0; i < 8; i++) {
        if (v[i] >= CUT0 && v[i] < CUT1)      d_idx0[p0++] = t * 8 + i;
        else if (v[i] >= CUT1)                d_idx1[p1++] = t * 8 + i;
    }
    if (t == 1023) { d_counts[0] = s0[1023]; d_counts[1] = s1[1023]; }
}

// ---------------- generic fp32 GEMM: C = A @ B^T (+bias) -----------------
// Inner loop uses packed fma.rn.f32x2 (2 fp32 FMA / instruction).
// Accumulators: acc[j][ip] = f32x2 over row-pair (i=2ip, 2ip+1), column j.
__global__ void __launch_bounds__(256, 2) sgemm_abt_kernel(
    const float* __restrict__ A, const int* __restrict__ rowidx, int lda,
    const float* __restrict__ B, int N, int K,
    float* __restrict__ Cbase, long long coff, int add_n0_off,
    int ldc, const float* __restrict__ bias,
    int Mstatic, int msel)
{
    int M = (msel == 0) ? Mstatic : d_counts[msel - 1];
    int brow0 = blockIdx.y * 128;
    if (brow0 >= M) return;
    int bcol0 = blockIdx.x * 128;

    __shared__ float As[8][128];
    __shared__ float Bs[8][128];

    int tid = threadIdx.x;
    int tx = tid & 15, ty = tid >> 4;

    // load mapping: 256 threads, one float4 of A and one of B each
    int lr  = tid >> 1;          // 0..127 (tile row)
    int lc4 = (tid & 1) * 4;     // 0 or 4 (k offset)

    int arow  = brow0 + lr;
    bool aval = (arow < M);
    int aprow = aval ? (rowidx ? rowidx[arow] : arow) : 0;
    const float* Arow = A + (size_t)aprow * lda + lc4;

    int bcol = bcol0 + lr;
    int bcc  = bcol < N ? bcol : (N - 1);
    const float* Brow = B + (size_t)bcc * K + lc4;

    unsigned long long acc[8][4];
#pragma unroll
    for (int j = 0; j < 8; j++)
#pragma unroll
        for (int ip = 0; ip < 4; ip++) acc[j][ip] = 0ull;

    for (int k0 = 0; k0 < K; k0 += 8) {
        float4 av = aval ? *(const float4*)(Arow + k0)
                         : make_float4(0.f, 0.f, 0.f, 0.f);
        float4 bv = *(const float4*)(Brow + k0);
        As[lc4 + 0][lr] = av.x; As[lc4 + 1][lr] = av.y;
        As[lc4 + 2][lr] = av.z; As[lc4 + 3][lr] = av.w;
        Bs[lc4 + 0][lr] = bv.x; Bs[lc4 + 1][lr] = bv.y;
        Bs[lc4 + 2][lr] = bv.z; Bs[lc4 + 3][lr] = bv.w;
        __syncthreads();
#pragma unroll
        for (int k = 0; k < 8; k++) {
            float4 a0 = *(const float4*)&As[k][ty * 8];
            float4 a1 = *(const float4*)&As[k][ty * 8 + 4];
            float4 b0 = *(const float4*)&Bs[k][tx * 8];
            float4 b1 = *(const float4*)&Bs[k][tx * 8 + 4];
            unsigned long long a2[4], b2[8];
            PACK2(a2[0], a0.x, a0.y);
            PACK2(a2[1], a0.z, a0.w);
            PACK2(a2[2], a1.x, a1.y);
            PACK2(a2[3], a1.z, a1.w);
            PACK2(b2[0], b0.x, b0.x);
            PACK2(b2[1], b0.y, b0.y);
            PACK2(b2[2], b0.z, b0.z);
            PACK2(b2[3], b0.w, b0.w);
            PACK2(b2[4], b1.x, b1.x);
            PACK2(b2[5], b1.y, b1.y);
            PACK2(b2[6], b1.z, b1.z);
            PACK2(b2[7], b1.w, b1.w);
#pragma unroll
            for (int j = 0; j < 8; j++)
#pragma unroll
                for (int ip = 0; ip < 4; ip++)
                    FMA2(acc[j][ip], a2[ip], b2[j]);
        }
        __syncthreads();
    }

    float* C = Cbase + coff +
               (add_n0_off ? (long long)d_counts[0] * (long long)NCOLS0 : 0ll);
#pragma unroll
    for (int ip = 0; ip < 4; ip++) {
        int r0 = brow0 + ty * 8 + 2 * ip;
        int r1 = r0 + 1;
#pragma unroll
        for (int j = 0; j < 8; j++) {
            int c = bcol0 + tx * 8 + j;
            if (c >= N) continue;
            float lo, hi;
            UNPACK2(lo, hi, acc[j][ip]);
            float bb = bias ? bias[c] : 0.f;
            if (r0 < M) C[(size_t)r0 * ldc + c] = lo + bb;
            if (r1 < M) C[(size_t)r1 * ldc + c] = hi + bb;
        }
    }
}

// -------- head tail columns: out[:, 2000:2002] = hidden @ tailW^T + tb ---
__global__ void head_tail_kernel(const float* __restrict__ hidden,
                                 const float* __restrict__ tw,
                                 const float* __restrict__ tb,
                                 float* __restrict__ out) {
    int row  = blockIdx.x * 4 + (threadIdx.x >> 5);
    int lane = threadIdx.x & 31;
    const float* h = hidden + (size_t)row * HDIM;
    float s0 = 0.f, s1 = 0.f;
#pragma unroll
    for (int i = lane; i < HDIM; i += 32) {
        float x = h[i];
        s0 += x * tw[i];
        s1 += x * tw[HDIM + i];
    }
#pragma unroll
    for (int o = 16; o > 0; o >>= 1) {
        s0 += __shfl_xor_sync(0xffffffffu, s0, o);
        s1 += __shfl_xor_sync(0xffffffffu, s1, o);
    }
    if (lane == 0) {
        out[(size_t)row * HEADC + CUT0]     = s0 + tb[0];
        out[(size_t)row * HEADC + CUT0 + 1] = s1 + tb[1];
    }
}

extern "C" void kernel_launch(void* const* d_in, const int* in_sizes, int n_in,
                              void* d_out, int out_size)
{
    (void)in_sizes; (void)n_in; (void)out_size;
    const float* hidden = (const float*)d_in[0];
    const float* embed  = (const float*)d_in[1];
    const float* tailW  = (const float*)d_in[2];
    const float* tailb  = (const float*)d_in[3];
    const float* sbias  = (const float*)d_in[4];
    const float* bias0  = (const float*)d_in[5];
    const float* bias1  = (const float*)d_in[6];
    const float* down0  = (const float*)d_in[7];
    const float* down1  = (const float*)d_in[8];
    const int*   targets = (const int*)d_in[9];
    float* out = (float*)d_out;

    float *p_dec0, *p_dec1, *p_h0, *p_h1;
    int *p_idx0, *p_idx1;
    cudaGetSymbolAddress((void**)&p_dec0, d_dec0);
    cudaGetSymbolAddress((void**)&p_dec1, d_dec1);
    cudaGetSymbolAddress((void**)&p_h0,   d_h0);
    cudaGetSymbolAddress((void**)&p_h1,   d_h1);
    cudaGetSymbolAddress((void**)&p_idx0, d_idx0);
    cudaGetSymbolAddress((void**)&p_idx1, d_idx1);

    dim3 blk(256);

    // 1. partition targets -> idx0/idx1 + counts (dtype-agnostic)
    scan_targets_kernel<<<1, 1024>>>(targets);

    // 2. head shortlist: [8192 x 2000] = hidden @ embed[:2000]^T + sbias
    sgemm_abt_kernel<<<dim3(16, 64), blk>>>(hidden, nullptr, HDIM,
                                            embed, CUT0, HDIM,
                                            out, 0, 0, HEADC, sbias,
                                            BATCH, 0);
    // 3. head tail columns
    head_tail_kernel<<<BATCH / 4, 128>>>(hidden, tailW, tailb, out);

    // 4. dec0 [18000 x 1024] = embed[2000:20000] @ down0^T
    sgemm_abt_kernel<<<dim3(8, 141), blk>>>(embed + (size_t)CUT0 * HDIM, nullptr, HDIM,
                                            down0, HDIM, HDIM,
                                            p_dec0, 0, 0, HDIM, nullptr,
                                            NCOLS0, 0);
    // 5. dec1 [30000 x 256] = embed[20000:50000] @ down1^T
    sgemm_abt_kernel<<<dim3(2, 235), blk>>>(embed + (size_t)CUT1 * HDIM, nullptr, HDIM,
                                            down1, H4, HDIM,
                                            p_dec1, 0, 0, H4, nullptr,
                                            NCOLS1, 0);
    // 6. h0 [n0 x 1024] = hidden[idx0] @ down0^T   (gathered A)
    sgemm_abt_kernel<<<dim3(8, 64), blk>>>(hidden, p_idx0, HDIM,
                                           down0, HDIM, HDIM,
                                           p_h0, 0, 0, HDIM, nullptr,
                                           0, 1);
    // 7. out0 [n0 x 18000] = h0 @ dec0^T + bias0
    sgemm_abt_kernel<<<dim3(141, 64), blk>>>(p_h0, nullptr, HDIM,
                                             p_dec0, NCOLS0, HDIM,
                                             out, (long long)BATCH * HEADC, 0,
                                             NCOLS0, bias0, 0, 1);
    // 8. h1 [n1 x 256] = hidden[idx1] @ down1^T   (gathered A)
    sgemm_abt_kernel<<<dim3(2, 64), blk>>>(hidden, p_idx1, HDIM,
                                           down1, H4, HDIM,
                                           p_h1, 0, 0, H4, nullptr,
                                           0, 2);
    // 9. out1 [n1 x 30000] = h1 @ dec1^T + bias1 (offset depends on n0)
    sgemm_abt_kernel<<<dim3(235, 64), blk>>>(p_h1, nullptr, H4,
                                             p_dec1, NCOLS1, H4,
                                             out, (long long)BATCH * HEADC, 1,
                                             NCOLS1, bias1, 0, 2);
}

// round 5
// speedup vs baseline: 2.6806x; 2.6806x over previous
#include <cuda_runtime.h>
#include <cuda_bf16.h>
#include <cstdint>

#define CUT0   2000
#define CUT1   20000
#define BATCH  8192
#define HDIM   1024
#define H4     256
#define NCOLS0 18000
#define NCOLS1 30000
#define HEADC  2002

#define BM 128
#define BN 128
#define BK 32
#define LDS 40                 // halves per smem row (32 + 8 pad)
#define OPBYTES 10240          // 128*40*2
#define BUFBYTES 40960         // 4 operands
#define SMEM_BYTES 81920       // 2 buffers

// ---------------- device scratch (no allocations allowed) ----------------
__device__ int d_idx0[BATCH];
__device__ int d_idx1[BATCH];
__device__ int d_counts[2];

__device__ __nv_bfloat16 g_hidh[BATCH * HDIM],  g_hidl[BATCH * HDIM];
__device__ __nv_bfloat16 g_embh[50000 * HDIM],  g_embl[50000 * HDIM];
__device__ __nv_bfloat16 g_d0h[HDIM * HDIM],    g_d0l[HDIM * HDIM];
__device__ __nv_bfloat16 g_d1h[H4 * HDIM],      g_d1l[H4 * HDIM];
__device__ __nv_bfloat16 g_dec0h[NCOLS0 * HDIM], g_dec0l[NCOLS0 * HDIM];
__device__ __nv_bfloat16 g_dec1h[NCOLS1 * H4],   g_dec1l[NCOLS1 * H4];
__device__ __nv_bfloat16 g_h0h[BATCH * HDIM],   g_h0l[BATCH * HDIM];
__device__ __nv_bfloat16 g_h1h[BATCH * H4],     g_h1l[BATCH * H4];

// ---------------- PTX helpers --------------------------------------------
__device__ __forceinline__ uint32_t smem_u32(const void* p) {
    uint32_t a;
    asm("{ .reg .u64 t; cvta.to.shared.u64 t, %1; cvt.u32.u64 %0, t; }"
        : "=r"(a) : "l"(p));
    return a;
}
#define CPA(dst, src) \
    asm volatile("cp.async.cg.shared.global [%0], [%1], 16;" \
                 :: "r"(dst), "l"(src) : "memory")
#define CPA_COMMIT() asm volatile("cp.async.commit_group;" ::: "memory")
#define CPA_WAIT(n)  asm volatile("cp.async.wait_group %0;" :: "n"(n) : "memory")

#define LDSM4(r, addr) \
    asm volatile("ldmatrix.sync.aligned.m8n8.x4.shared.b16 {%0,%1,%2,%3}, [%4];" \
                 : "=r"((r)[0]), "=r"((r)[1]), "=r"((r)[2]), "=r"((r)[3]) \
                 : "r"(addr))

#define MMA_BF16(c, a, b0, b1) \
    asm volatile("mma.sync.aligned.m16n8k16.row.col.f32.bf16.bf16.f32 " \
                 "{%0,%1,%2,%3}, {%4,%5,%6,%7}, {%8,%9}, {%0,%1,%2,%3};" \
                 : "+f"((c)[0]), "+f"((c)[1]), "+f"((c)[2]), "+f"((c)[3]) \
                 : "r"((a)[0]), "r"((a)[1]), "r"((a)[2]), "r"((a)[3]), \
                   "r"(b0), "r"(b1))

// ---------------- partition targets (int32/int64 agnostic) ---------------
__global__ void scan_targets_kernel(const int* __restrict__ tw) {
    __shared__ int s0[1024], s1[1024];
    __shared__ int anynz;
    int t = threadIdx.x;
    if (t == 0) anynz = 0;
    __syncthreads();
    int nz = 0;
    for (int i = t; i < 4096; i += 1024) nz |= (tw[2 * i + 1] != 0);
    if (nz) atomicOr(&anynz, 1);
    __syncthreads();
    int stride = anynz ? 1 : 2;

    int v[8]; int c0 = 0, c1 = 0;
#pragma unroll
    for (int i = 0; i < 8; i++) {
        v[i] = tw[(t * 8 + i) * stride];
        c0 += (v[i] >= CUT0 && v[i] < CUT1) ? 1 : 0;
        c1 += (v[i] >= CUT1) ? 1 : 0;
    }
    s0[t] = c0; s1[t] = c1;
    __syncthreads();
    for (int off = 1; off < 1024; off <<= 1) {
        int a0 = (t >= off) ? s0[t - off] : 0;
        int a1 = (t >= off) ? s1[t - off] : 0;
        __syncthreads();
        s0[t] += a0; s1[t] += a1;
        __syncthreads();
    }
    int p0 = s0[t] - c0, p1 = s1[t] - c1;
#pragma unroll
    for (int i = 0; i < 8; i++) {
        if (v[i] >= CUT0 && v[i] < CUT1)      d_idx0[p0++] = t * 8 + i;
        else if (v[i] >= CUT1)                d_idx1[p1++] = t * 8 + i;
    }
    if (t == 1023) { d_counts[0] = s0[1023]; d_counts[1] = s1[1023]; }
}

// ---------------- fp32 -> bf16 hi/lo pair conversion ----------------------
__global__ void conv_pair_kernel(const float4* __restrict__ src,
                                 __nv_bfloat16* __restrict__ hi,
                                 __nv_bfloat16* __restrict__ lo, int n4) {
    int i = blockIdx.x * blockDim.x + threadIdx.x;
    int stride = gridDim.x * blockDim.x;
    for (; i < n4; i += stride) {
        float4 v = src[i];
        __nv_bfloat16 h0 = __float2bfloat16(v.x), h1 = __float2bfloat16(v.y);
        __nv_bfloat16 h2 = __float2bfloat16(v.z), h3 = __float2bfloat16(v.w);
        __nv_bfloat16 l0 = __float2bfloat16(v.x - __bfloat162float(h0));
        __nv_bfloat16 l1 = __float2bfloat16(v.y - __bfloat162float(h1));
        __nv_bfloat16 l2 = __float2bfloat16(v.z - __bfloat162float(h2));
        __nv_bfloat16 l3 = __float2bfloat16(v.w - __bfloat162float(h3));
        __nv_bfloat162* ph = (__nv_bfloat162*)(hi + (size_t)i * 4);
        __nv_bfloat162* pl = (__nv_bfloat162*)(lo + (size_t)i * 4);
        ph[0] = __nv_bfloat162(h0, h1); ph[1] = __nv_bfloat162(h2, h3);
        pl[0] = __nv_bfloat162(l0, l1); pl[1] = __nv_bfloat162(l2, l3);
    }
}

// ---------------- HMMA split-bf16 GEMM: C = A @ B^T (+bias) --------------
// A[MxK], B[NxK] as bf16 hi/lo pairs; 3 mma passes (hh, lh, hl) accumulate
// in fp32 registers. CTA tile 128x128xBK32, warps 4(M)x2(N), warp 32x64.
__global__ void __launch_bounds__(256, 1) hmma_gemm_kernel(
    const __nv_bfloat16* __restrict__ Ah, const __nv_bfloat16* __restrict__ Al,
    const int* __restrict__ rowidx,
    const __nv_bfloat16* __restrict__ Bh, const __nv_bfloat16* __restrict__ Bl,
    int N, int K,
    float* __restrict__ Cf, long long coff, int add_n0_off, int ldc,
    const float* __restrict__ bias,
    __nv_bfloat16* __restrict__ Chi, __nv_bfloat16* __restrict__ Clo,
    int Mstatic, int msel)
{
    int M = (msel == 0) ? Mstatic : d_counts[msel - 1];
    int brow0 = blockIdx.y * BM;
    if (brow0 >= M) return;
    int bcol0 = blockIdx.x * BN;

    extern __shared__ char smem[];
    uint32_t sbase = smem_u32(smem);
    int tid = threadIdx.x, lane = tid & 31, wid = tid >> 5;
    int m0w = (wid >> 1) * 32, n0w = (wid & 1) * 64;

    // ---- gmem load plan: 2 units/thread, 4 operands each -----------------
    int u1 = tid, u2 = tid + 256;
    int r1 = u1 >> 2, kq1 = u1 & 3, r2 = u2 >> 2, kq2 = u2 & 3;
    int ga1 = brow0 + r1; if (ga1 >= M) ga1 = M - 1;
    int ga2 = brow0 + r2; if (ga2 >= M) ga2 = M - 1;
    if (rowidx) { ga1 = rowidx[ga1]; ga2 = rowidx[ga2]; }
    int gb1 = bcol0 + r1; if (gb1 >= N) gb1 = N - 1;
    int gb2 = bcol0 + r2; if (gb2 >= N) gb2 = N - 1;
    const __nv_bfloat16* pA1h = Ah + (size_t)ga1 * K + kq1 * 8;
    const __nv_bfloat16* pA1l = Al + (size_t)ga1 * K + kq1 * 8;
    const __nv_bfloat16* pB1h = Bh + (size_t)gb1 * K + kq1 * 8;
    const __nv_bfloat16* pB1l = Bl + (size_t)gb1 * K + kq1 * 8;
    const __nv_bfloat16* pA2h = Ah + (size_t)ga2 * K + kq2 * 8;
    const __nv_bfloat16* pA2l = Al + (size_t)ga2 * K + kq2 * 8;
    const __nv_bfloat16* pB2h = Bh + (size_t)gb2 * K + kq2 * 8;
    const __nv_bfloat16* pB2l = Bl + (size_t)gb2 * K + kq2 * 8;
    uint32_t sm1 = (uint32_t)(r1 * LDS + kq1 * 8) * 2;
    uint32_t sm2 = (uint32_t)(r2 * LDS + kq2 * 8) * 2;

    float acc[2][8][4];
#pragma unroll
    for (int mi = 0; mi < 2; mi++)
#pragma unroll
        for (int nf = 0; nf < 8; nf++)
#pragma unroll
            for (int e = 0; e < 4; e++) acc[mi][nf][e] = 0.f;

    int NCk = K >> 5;

    // prefetch chunk 0
    {
        uint32_t b = sbase;
        CPA(b + 0 * OPBYTES + sm1, pA1h); CPA(b + 1 * OPBYTES + sm1, pA1l);
        CPA(b + 2 * OPBYTES + sm1, pB1h); CPA(b + 3 * OPBYTES + sm1, pB1l);
        CPA(b + 0 * OPBYTES + sm2, pA2h); CPA(b + 1 * OPBYTES + sm2, pA2l);
        CPA(b + 2 * OPBYTES + sm2, pB2h); CPA(b + 3 * OPBYTES + sm2, pB2l);
        CPA_COMMIT();
    }

    int lrow = lane & 15, lk = (lane >> 4) * 8;

    for (int c = 0; c < NCk; c++) {
        uint32_t buf = sbase + (uint32_t)(c & 1) * BUFBYTES;
        if (c + 1 < NCk) {
            int k0 = (c + 1) * BK;
            uint32_t b = sbase + (uint32_t)((c + 1) & 1) * BUFBYTES;
            CPA(b + 0 * OPBYTES + sm1, pA1h + k0); CPA(b + 1 * OPBYTES + sm1, pA1l + k0);
            CPA(b + 2 * OPBYTES + sm1, pB1h + k0); CPA(b + 3 * OPBYTES + sm1, pB1l + k0);
            CPA(b + 0 * OPBYTES + sm2, pA2h + k0); CPA(b + 1 * OPBYTES + sm2, pA2l + k0);
            CPA(b + 2 * OPBYTES + sm2, pB2h + k0); CPA(b + 3 * OPBYTES + sm2, pB2l + k0);
            CPA_COMMIT();
            CPA_WAIT(1);
        } else {
            CPA_WAIT(0);
        }
        __syncthreads();

#pragma unroll
        for (int ki = 0; ki < 2; ki++) {
            uint32_t koffb = (uint32_t)(ki * 16 + lk) * 2;
            uint32_t ah[2][4], al[2][4];
#pragma unroll
            for (int mi = 0; mi < 2; mi++) {
                uint32_t ro = (uint32_t)((m0w + mi * 16 + lrow) * LDS) * 2 + koffb;
                LDSM4(ah[mi], buf + 0 * OPBYTES + ro);
                LDSM4(al[mi], buf + 1 * OPBYTES + ro);
            }
#pragma unroll
            for (int np = 0; np < 4; np++) {
                uint32_t ro = (uint32_t)((n0w + np * 16 + lrow) * LDS) * 2 + koffb;
                uint32_t bh[4], bl[4];
                LDSM4(bh, buf + 2 * OPBYTES + ro);
                LDSM4(bl, buf + 3 * OPBYTES + ro);
#pragma unroll
                for (int mi = 0; mi < 2; mi++) {
                    MMA_BF16(acc[mi][np * 2],     ah[mi], bh[0], bh[2]);
                    MMA_BF16(acc[mi][np * 2],     al[mi], bh[0], bh[2]);
                    MMA_BF16(acc[mi][np * 2],     ah[mi], bl[0], bl[2]);
                    MMA_BF16(acc[mi][np * 2 + 1], ah[mi], bh[1], bh[3]);
                    MMA_BF16(acc[mi][np * 2 + 1], al[mi], bh[1], bh[3]);
                    MMA_BF16(acc[mi][np * 2 + 1], ah[mi], bl[1], bl[3]);
                }
            }
        }
        __syncthreads();
    }

    // ---- epilogue ---------------------------------------------------------
    float* Cdst = Cf ? (Cf + coff +
        (add_n0_off ? (long long)d_counts[0] * (long long)NCOLS0 : 0ll)) : nullptr;
#pragma unroll
    for (int mi = 0; mi < 2; mi++) {
        int m = brow0 + m0w + mi * 16 + (lane >> 2);
#pragma unroll
        for (int nf = 0; nf < 8; nf++) {
            int n = bcol0 + n0w + nf * 8 + (lane & 3) * 2;
            if (n >= N) continue;
            float v0 = acc[mi][nf][0], v1 = acc[mi][nf][1];
            float v2 = acc[mi][nf][2], v3 = acc[mi][nf][3];
            if (Cdst) {
                float b0 = bias ? bias[n] : 0.f, b1 = bias ? bias[n + 1] : 0.f;
                if (m < M) {
                    Cdst[(size_t)m * ldc + n]     = v0 + b0;
                    Cdst[(size_t)m * ldc + n + 1] = v1 + b1;
                }
                if (m + 8 < M) {
                    Cdst[(size_t)(m + 8) * ldc + n]     = v2 + b0;
                    Cdst[(size_t)(m + 8) * ldc + n + 1] = v3 + b1;
                }
            } else {
                if (m < M) {
                    __nv_bfloat16 h0 = __float2bfloat16(v0);
                    __nv_bfloat16 h1 = __float2bfloat16(v1);
                    __nv_bfloat16 l0 = __float2bfloat16(v0 - __bfloat162float(h0));
                    __nv_bfloat16 l1 = __float2bfloat16(v1 - __bfloat162float(h1));
                    *(__nv_bfloat162*)(Chi + (size_t)m * ldc + n) = __nv_bfloat162(h0, h1);
                    *(__nv_bfloat162*)(Clo + (size_t)m * ldc + n) = __nv_bfloat162(l0, l1);
                }
                if (m + 8 < M) {
                    __nv_bfloat16 h2 = __float2bfloat16(v2);
                    __nv_bfloat16 h3 = __float2bfloat16(v3);
                    __nv_bfloat16 l2 = __float2bfloat16(v2 - __bfloat162float(h2));
                    __nv_bfloat16 l3 = __float2bfloat16(v3 - __bfloat162float(h3));
                    *(__nv_bfloat162*)(Chi + (size_t)(m + 8) * ldc + n) = __nv_bfloat162(h2, h3);
                    *(__nv_bfloat162*)(Clo + (size_t)(m + 8) * ldc + n) = __nv_bfloat162(l2, l3);
                }
            }
        }
    }
}

// -------- head tail columns: out[:, 2000:2002] ----------------------------
__global__ void head_tail_kernel(const float* __restrict__ hidden,
                                 const float* __restrict__ tw,
                                 const float* __restrict__ tb,
                                 float* __restrict__ out) {
    int row  = blockIdx.x * 4 + (threadIdx.x >> 5);
    int lane = threadIdx.x & 31;
    const float* h = hidden + (size_t)row * HDIM;
    float s0 = 0.f, s1 = 0.f;
    for (int i = lane; i < HDIM; i += 32) {
        float x = h[i];
        s0 += x * tw[i];
        s1 += x * tw[HDIM + i];
    }
#pragma unroll
    for (int o = 16; o > 0; o >>= 1) {
        s0 += __shfl_xor_sync(0xffffffffu, s0, o);
        s1 += __shfl_xor_sync(0xffffffffu, s1, o);
    }
    if (lane == 0) {
        out[(size_t)row * HEADC + CUT0]     = s0 + tb[0];
        out[(size_t)row * HEADC + CUT0 + 1] = s1 + tb[1];
    }
}

extern "C" void kernel_launch(void* const* d_in, const int* in_sizes, int n_in,
                              void* d_out, int out_size)
{
    (void)in_sizes; (void)n_in; (void)out_size;
    const float* hidden = (const float*)d_in[0];
    const float* embed  = (const float*)d_in[1];
    const float* tailW  = (const float*)d_in[2];
    const float* tailb  = (const float*)d_in[3];
    const float* sbias  = (const float*)d_in[4];
    const float* bias0  = (const float*)d_in[5];
    const float* bias1  = (const float*)d_in[6];
    const float* down0  = (const float*)d_in[7];
    const float* down1  = (const float*)d_in[8];
    const int*   targets = (const int*)d_in[9];
    float* out = (float*)d_out;

    __nv_bfloat16 *hidh, *hidl, *embh, *embl, *d0h, *d0l, *d1h, *d1l;
    __nv_bfloat16 *dec0h, *dec0l, *dec1h, *dec1l, *h0h, *h0l, *h1h, *h1l;
    int *idx0, *idx1;
    cudaGetSymbolAddress((void**)&hidh, g_hidh);  cudaGetSymbolAddress((void**)&hidl, g_hidl);
    cudaGetSymbolAddress((void**)&embh, g_embh);  cudaGetSymbolAddress((void**)&embl, g_embl);
    cudaGetSymbolAddress((void**)&d0h, g_d0h);    cudaGetSymbolAddress((void**)&d0l, g_d0l);
    cudaGetSymbolAddress((void**)&d1h, g_d1h);    cudaGetSymbolAddress((void**)&d1l, g_d1l);
    cudaGetSymbolAddress((void**)&dec0h, g_dec0h); cudaGetSymbolAddress((void**)&dec0l, g_dec0l);
    cudaGetSymbolAddress((void**)&dec1h, g_dec1h); cudaGetSymbolAddress((void**)&dec1l, g_dec1l);
    cudaGetSymbolAddress((void**)&h0h, g_h0h);    cudaGetSymbolAddress((void**)&h0l, g_h0l);
    cudaGetSymbolAddress((void**)&h1h, g_h1h);    cudaGetSymbolAddress((void**)&h1l, g_h1l);
    cudaGetSymbolAddress((void**)&idx0, d_idx0);  cudaGetSymbolAddress((void**)&idx1, d_idx1);

    cudaFuncSetAttribute(hmma_gemm_kernel,
                         cudaFuncAttributeMaxDynamicSharedMemorySize, SMEM_BYTES);

    // 1. partition targets
    scan_targets_kernel<<<1, 1024>>>(targets);

    // 2. operand conversions fp32 -> bf16 hi/lo
    conv_pair_kernel<<<2048, 256>>>((const float4*)hidden, hidh, hidl, BATCH * HDIM / 4);
    conv_pair_kernel<<<2048, 256>>>((const float4*)embed,  embh, embl, 50000 * HDIM / 4);
    conv_pair_kernel<<<512, 256>>>((const float4*)down0,   d0h,  d0l,  HDIM * HDIM / 4);
    conv_pair_kernel<<<256, 256>>>((const float4*)down1,   d1h,  d1l,  H4 * HDIM / 4);

    // 3. head: [8192 x 2000] = hidden @ emb[:2000]^T + sbias
    hmma_gemm_kernel<<<dim3(16, 64), 256, SMEM_BYTES>>>(
        hidh, hidl, nullptr, embh, embl, CUT0, HDIM,
        out, 0, 0, HEADC, sbias, nullptr, nullptr, BATCH, 0);
    head_tail_kernel<<<BATCH / 4, 128>>>(hidden, tailW, tailb, out);

    // 4. dec0 [18000 x 1024] = emb[2000:20000] @ down0^T -> bf16 pair
    hmma_gemm_kernel<<<dim3(8, 141), 256, SMEM_BYTES>>>(
        embh + (size_t)CUT0 * HDIM, embl + (size_t)CUT0 * HDIM, nullptr,
        d0h, d0l, HDIM, HDIM,
        nullptr, 0, 0, HDIM, nullptr, dec0h, dec0l, NCOLS0, 0);

    // 5. dec1 [30000 x 256] = emb[20000:] @ down1^T -> bf16 pair
    hmma_gemm_kernel<<<dim3(2, 235), 256, SMEM_BYTES>>>(
        embh + (size_t)CUT1 * HDIM, embl + (size_t)CUT1 * HDIM, nullptr,
        d1h, d1l, H4, HDIM,
        nullptr, 0, 0, H4, nullptr, dec1h, dec1l, NCOLS1, 0);

    // 6. h0 [n0 x 1024] = hidden[idx0] @ down0^T -> bf16 pair
    hmma_gemm_kernel<<<dim3(8, 64), 256, SMEM_BYTES>>>(
        hidh, hidl, idx0, d0h, d0l, HDIM, HDIM,
        nullptr, 0, 0, HDIM, nullptr, h0h, h0l, 0, 1);

    // 7. out0 [n0 x 18000] = h0 @ dec0^T + bias0
    hmma_gemm_kernel<<<dim3(141, 64), 256, SMEM_BYTES>>>(
        h0h, h0l, nullptr, dec0h, dec0l, NCOLS0, HDIM,
        out, (long long)BATCH * HEADC, 0, NCOLS0, bias0, nullptr, nullptr, 0, 1);

    // 8. h1 [n1 x 256] = hidden[idx1] @ down1^T -> bf16 pair
    hmma_gemm_kernel<<<dim3(2, 64), 256, SMEM_BYTES>>>(
        hidh, hidl, idx1, d1h, d1l, H4, HDIM,
        nullptr, 0, 0, H4, nullptr, h1h, h1l, 0, 2);

    // 9. out1 [n1 x 30000] = h1 @ dec1^T + bias1 (offset depends on n0)
    hmma_gemm_kernel<<<dim3(235, 64), 256, SMEM_BYTES>>>(
        h1h, h1l, nullptr, dec1h, dec1l, NCOLS1, H4,
        out, (long long)BATCH * HEADC, 1, NCOLS1, bias1, nullptr, nullptr, 0, 2);
}